// round 16
// baseline (speedup 1.0000x reference)
#include <cuda_runtime.h>
#include <cuda_bf16.h>
#include <math.h>
#include <stdint.h>

#define HID   256
#define NB    128
#define HW    32
#define NBLK  144            // 9 cell-slots x 16 j-slices, persistent (1/SM)
#define CSLOTS 9
#define THREADS 256
#define PITCH 528            // bytes per bf16 tile row (264 bf16; ldmatrix conflict-free)

// ---- smem layout (bytes) ----
#define SM_CONST 0                              // bias[64], wih[64] floats (512 B)
#define SM_A_HI  1024                           // A hi: 64 x 264 bf16 (33792 B)
#define SM_A_LO  (SM_A_HI + 64 * PITCH)
#define SM_W_HI  (SM_A_LO + 64 * PITCH)         // W hi: 64 x 264 bf16, rows n = jt*4+type
#define SM_W_LO  (SM_W_HI + 64 * PITCH)
#define SMEM_TOTAL (SM_W_LO + 64 * PITCH)       // 136192 B

// Cell state s, layout [cell][b][j]. 134 MB scratch.
__device__ float g_s[(size_t)HW * HW * NB * HID];
// grid barrier
__device__ int      g_bar_count;
__device__ unsigned g_bar_gen;

__device__ __forceinline__ uint32_t smem_u32(const void* p) {
    uint32_t a;
    asm("{ .reg .u64 t; cvta.to.shared.u64 t, %1; cvt.u32.u64 %0, t; }" : "=r"(a) : "l"(p));
    return a;
}

// MUFU.TANH-based activations (single-MUFU each).
__device__ __forceinline__ float ftanh(float x) {
    float y;
    asm("tanh.approx.f32 %0, %1;" : "=f"(y) : "f"(x));
    return y;
}
// sigmoid(x) = 0.5*tanh(x/2) + 0.5
__device__ __forceinline__ float fsigmoid(float x) {
    return fmaf(0.5f, ftanh(0.5f * x), 0.5f);
}

__device__ __forceinline__ void ldm_x4(uint32_t* r, uint32_t addr) {
    asm volatile("ldmatrix.sync.aligned.m8n8.x4.shared.b16 {%0,%1,%2,%3}, [%4];"
        : "=r"(r[0]), "=r"(r[1]), "=r"(r[2]), "=r"(r[3]) : "r"(addr));
}
__device__ __forceinline__ void mma_bf16(float* c, const uint32_t* a, uint32_t b0, uint32_t b1) {
    asm volatile(
        "mma.sync.aligned.m16n8k16.row.col.f32.bf16.bf16.f32 "
        "{%0,%1,%2,%3}, {%4,%5,%6,%7}, {%8,%9}, {%0,%1,%2,%3};"
        : "+f"(c[0]), "+f"(c[1]), "+f"(c[2]), "+f"(c[3])
        : "r"(a[0]), "r"(a[1]), "r"(a[2]), "r"(a[3]), "r"(b0), "r"(b1));
}

__device__ __forceinline__ uint32_t bf2u(__nv_bfloat162 v) {
    return *reinterpret_cast<uint32_t*>(&v);
}
// split float pair -> (hi bf16x2, lo bf16x2)
__device__ __forceinline__ void split2(float a, float b, uint32_t& hi, uint32_t& lo) {
    __nv_bfloat162 h = __floats2bfloat162_rn(a, b);
    float la = a - __low2float(h);
    float lb = b - __high2float(h);
    __nv_bfloat162 l = __floats2bfloat162_rn(la, lb);
    hi = bf2u(h); lo = bf2u(l);
}

__device__ __forceinline__ void grid_barrier() {
    __syncthreads();
    if (threadIdx.x == 0) {
        __threadfence();
        unsigned gen = *((volatile unsigned*)&g_bar_gen);
        int t = atomicAdd(&g_bar_count, 1);
        if (t == NBLK - 1) {
            g_bar_count = 0;
            __threadfence();
            atomicAdd(&g_bar_gen, 1u);
        } else {
            while (*((volatile unsigned*)&g_bar_gen) == gen) { }
        }
    }
    __syncthreads();
}

// Persistent MD-LSTM with HALF-CELL tasks. Block = 256 threads (8 warps,
// grid 4(M) x 2(N), warp tile m16 x n32). Task tile: M=64 batches x N=64
// gate rows (n = jt*4 + type; j = sb*16 + jt) x K=256, split-bf16 HMMA.
// Per diagonal: 2*n_d tasks round-robin over 9 cslots (finer balancing).
__global__ __launch_bounds__(THREADS, 1)
void mdlstm_mma(const float* __restrict__ x,
                const float* __restrict__ w_ih,
                const float* __restrict__ w_hh,
                const float* __restrict__ bias,
                float*       __restrict__ out)
{
    extern __shared__ unsigned char smem[];
    const uint32_t smb  = smem_u32(smem);
    const int tid  = threadIdx.x;
    const int lane = tid & 31;
    const int wrp  = tid >> 5;            // 0..7
    const int mq   = wrp & 3;             // m-quad within 64-row task tile
    const int nh   = wrp >> 2;            // n-half: jt range nh*8..nh*8+7
    const int sb    = blockIdx.x & 15;    // j-slice
    const int cslot = blockIdx.x >> 4;    // 0..8

    // ---- one-time: W slice split into smem hi/lo, rows n = jt*4 + type ----
    {
        const int n    = tid >> 2;                 // 0..63
        const int kc   = (tid & 3) * 64;
        const int type = n & 3, jt = n >> 2;
        const int j    = sb * 16 + jt;
        const float* src = w_hh + ((size_t)(type * 256 + j) * 256 + kc);
        unsigned char* dhi = smem + SM_W_HI + n * PITCH + kc * 2;
        unsigned char* dlo = smem + SM_W_LO + n * PITCH + kc * 2;
        #pragma unroll 4
        for (int i = 0; i < 16; i++) {
            float4 v = *(const float4*)(src + i * 4);
            uint32_t h0, l0, h1, l1;
            split2(v.x, v.y, h0, l0);
            split2(v.z, v.w, h1, l1);
            *(uint2*)(dhi + i * 8) = make_uint2(h0, h1);
            *(uint2*)(dlo + i * 8) = make_uint2(l0, l1);
        }
    }
    if (tid < 64) {
        const int type = tid >> 4, jt = tid & 15;
        const int j = sb * 16 + jt;
        ((float*)(smem + SM_CONST))[tid]      = bias[type * 256 + j];   // sbias[type*16+jt]
        ((float*)(smem + SM_CONST))[64 + tid] = w_ih[type * 256 + j];
    }
    __syncthreads();

    // per-lane ldmatrix address components (A rows 0..63 of task tile)
    const uint32_t a_off  = (uint32_t)(mq * 16 + (lane & 15)) * PITCH + (lane >> 4) * 16;
    const uint32_t b_off0 = (uint32_t)(nh * 32 + (lane & 15)) * PITCH + (lane >> 4) * 16;
    const uint32_t b_off1 = b_off0 + 16 * PITCH;

    const int q  = lane & 3;
    const int rr = lane >> 2;             // 0..7
    const int p  = q & 1;                 // 0: holds (i,f) -> row rr; 1: (g,o) -> row rr+8
    const float* sbias = (const float*)(smem + SM_CONST);
    const float* swih  = sbias + 64;

    const size_t img = (size_t)HW * HW * HID;

    for (int d = 0; d < 2 * HW - 1; d++) {
        const int n_d = (d < HW) ? (d + 1) : (2 * HW - 1 - d);
        const int r0  = (d > HW - 1) ? d - (HW - 1) : 0;

        for (int u = cslot; u < 2 * n_d; u += CSLOTS) {
            const int cell = u >> 1;
            const int half = u & 1;
            const int mbase = half * 64;
            const int r = r0 + cell, c = d - r;
            const int cell_id = r * HW + c;
            const bool has_up = (r > 0), has_left = (c > 0);

            float acc[4][4];
            #pragma unroll
            for (int f = 0; f < 4; f++)
                #pragma unroll
                for (int e = 0; e < 4; e++) acc[f][e] = 0.0f;

            if (has_up || has_left) {
                // ---- stage hsum rows mbase..mbase+63, split -> smem A hi/lo ----
                {
                    const int row = tid >> 2;            // 0..63
                    const int j0  = (tid & 3) * 64;
                    const int bglob = mbase + row;
                    const float* pu = out + (size_t)bglob * img
                                          + (size_t)(cell_id - HW) * HID + j0;
                    const float* pl = out + (size_t)bglob * img
                                          + (size_t)(cell_id - 1) * HID + j0;
                    unsigned char* ahi = smem + SM_A_HI + row * PITCH + j0 * 2;
                    unsigned char* alo = smem + SM_A_LO + row * PITCH + j0 * 2;
                    #pragma unroll 8
                    for (int i = 0; i < 16; i++) {
                        float4 v = make_float4(0.f, 0.f, 0.f, 0.f);
                        if (has_up) {
                            float4 uu = *(const float4*)(pu + i * 4);
                            v.x = uu.x; v.y = uu.y; v.z = uu.z; v.w = uu.w;
                        }
                        if (has_left) {
                            float4 ll = *(const float4*)(pl + i * 4);
                            v.x += ll.x; v.y += ll.y; v.z += ll.z; v.w += ll.w;
                        }
                        uint32_t h0, l0, h1, l1;
                        split2(v.x, v.y, h0, l0);
                        split2(v.z, v.w, h1, l1);
                        *(uint2*)(ahi + i * 8) = make_uint2(h0, h1);
                        *(uint2*)(alo + i * 8) = make_uint2(l0, l1);
                    }
                }
                __syncthreads();
            }

            // ---- prefetch epilogue operands before GEMM ----
            const size_t s_cur  = (size_t)cell_id * NB * HID;
            const size_t s_up   = (size_t)(cell_id - HW) * NB * HID;
            const size_t s_left = (size_t)(cell_id - 1) * NB * HID;
            const int b_ep = mbase + mq * 16 + rr + p * 8;
            const float xp = x[b_ep * (HW * HW) + cell_id];

            float pss[4];
            #pragma unroll
            for (int gg = 0; gg < 4; gg++) {
                const int jt = nh * 8 + gg * 2 + (q >> 1);
                const int j  = sb * 16 + jt;
                float ss = 0.0f;
                if (has_up)   ss += g_s[s_up   + (size_t)b_ep * HID + j];
                if (has_left) ss += g_s[s_left + (size_t)b_ep * HID + j];
                pss[gg] = ss;
            }

            if (has_up || has_left) {
                // ---- GEMM over K=256 in 16-wide steps ----
                #pragma unroll 2
                for (int kk = 0; kk < 16; kk++) {
                    const uint32_t ka = kk * 32;        // 16 bf16 = 32 B per k-step
                    uint32_t ah[4], al[4], bh[8], bl[8];
                    ldm_x4(ah,     smb + SM_A_HI + a_off  + ka);
                    ldm_x4(al,     smb + SM_A_LO + a_off  + ka);
                    ldm_x4(bh,     smb + SM_W_HI + b_off0 + ka);
                    ldm_x4(bh + 4, smb + SM_W_HI + b_off1 + ka);
                    ldm_x4(bl,     smb + SM_W_LO + b_off0 + ka);
                    ldm_x4(bl + 4, smb + SM_W_LO + b_off1 + ka);
                    // gg0=(bh0,bh2) gg1=(bh1,bh3) gg2=(bh4,bh6) gg3=(bh5,bh7)
                    #pragma unroll
                    for (int g = 0; g < 2; g++) {
                        #pragma unroll
                        for (int hh = 0; hh < 2; hh++) {
                            const int gg = g * 2 + hh;
                            const uint32_t f0h = bh[g * 4 + hh], f1h = bh[g * 4 + 2 + hh];
                            const uint32_t f0l = bl[g * 4 + hh], f1l = bl[g * 4 + 2 + hh];
                            mma_bf16(acc[gg], ah, f0h, f1h);
                            mma_bf16(acc[gg], ah, f0l, f1l);
                            mma_bf16(acc[gg], al, f0h, f1h);
                        }
                    }
                }
            }

            // ---- epilogue: pair (q, q^1) shares jt; bfly reunites 4 gates ----
            #pragma unroll
            for (int gg = 0; gg < 4; gg++) {
                const int jt = nh * 8 + gg * 2 + (q >> 1);
                const int j  = sb * 16 + jt;
                float* a = acc[gg];

                const float send0 = p ? a[0] : a[2];
                const float send1 = p ? a[1] : a[3];
                const float recv0 = __shfl_xor_sync(0xFFFFFFFFu, send0, 1);
                const float recv1 = __shfl_xor_sync(0xFFFFFFFFu, send1, 1);

                const float gi = p ? recv0 : a[0];
                const float gf = p ? recv1 : a[1];
                const float gG = p ? a[2]  : recv0;
                const float go = p ? a[3]  : recv1;

                const float vi = gi + sbias[jt]      + xp * swih[jt];
                const float vf = gf + sbias[16 + jt] + xp * swih[16 + jt];
                const float vg = gG + sbias[32 + jt] + xp * swih[32 + jt];
                const float vo = go + sbias[48 + jt] + xp * swih[48 + jt];

                const float iv = fsigmoid(vi);
                const float fv = fsigmoid(vf);
                const float gv = ftanh(vg);
                const float ov = fsigmoid(vo);

                const float sv = fv * pss[gg] + iv * gv;
                const float hv = ov * ftanh(sv);

                g_s[s_cur + (size_t)b_ep * HID + j] = sv;
                out[(size_t)b_ep * img + (size_t)cell_id * HID + j] = hv;
            }
            __syncthreads();   // all warps done with smem A before next staging
        }
        grid_barrier();
    }
}

extern "C" void kernel_launch(void* const* d_in, const int* in_sizes, int n_in,
                              void* d_out, int out_size) {
    const float* x    = (const float*)d_in[0];
    const float* w_ih = (const float*)d_in[1];
    const float* w_hh = (const float*)d_in[2];
    const float* bias = (const float*)d_in[3];
    float* out = (float*)d_out;

    cudaFuncSetAttribute(mdlstm_mma,
                         cudaFuncAttributeMaxDynamicSharedMemorySize, SMEM_TOTAL);
    mdlstm_mma<<<NBLK, THREADS, SMEM_TOTAL>>>(x, w_ih, w_hh, bias, out);
}

// round 17
// speedup vs baseline: 1.1045x; 1.1045x over previous
#include <cuda_runtime.h>
#include <cuda_bf16.h>
#include <math.h>
#include <stdint.h>

#define HID   256
#define NB    128
#define HW    32
#define NBLK  144            // 9 cell-slots x 16 j-slices, persistent (1/SM)
#define CSLOTS 9
#define THREADS 256
#define PITCH 528            // bytes per bf16 tile row (264 bf16; ldmatrix conflict-free)

// ---- smem layout (bytes) ----
#define SM_CONST 0                              // bias[64], wih[64] floats (512 B)
#define SM_A_HI  1024                           // A hi: 128 x 264 bf16 (67584 B)
#define SM_A_LO  (SM_A_HI + 128 * PITCH)
#define SM_W_HI  (SM_A_LO + 128 * PITCH)        // W hi: 64 x 264 bf16 (33792 B)
#define SM_W_LO  (SM_W_HI + 64 * PITCH)
#define SMEM_TOTAL (SM_W_LO + 64 * PITCH)       // 203776 B

// Cell state s, layout [cell][b][j]. 134 MB scratch.
__device__ float g_s[(size_t)HW * HW * NB * HID];
// grid barrier
__device__ int      g_bar_count;
__device__ unsigned g_bar_gen;

__device__ __forceinline__ uint32_t smem_u32(const void* p) {
    uint32_t a;
    asm("{ .reg .u64 t; cvta.to.shared.u64 t, %1; cvt.u32.u64 %0, t; }" : "=r"(a) : "l"(p));
    return a;
}

// MUFU.TANH-based activations (single-MUFU each).
__device__ __forceinline__ float ftanh(float x) {
    float y;
    asm("tanh.approx.f32 %0, %1;" : "=f"(y) : "f"(x));
    return y;
}
// sigmoid(x) = 0.5*tanh(x/2) + 0.5
__device__ __forceinline__ float fsigmoid(float x) {
    return fmaf(0.5f, ftanh(0.5f * x), 0.5f);
}

__device__ __forceinline__ void ldm_x4(uint32_t* r, uint32_t addr) {
    asm volatile("ldmatrix.sync.aligned.m8n8.x4.shared.b16 {%0,%1,%2,%3}, [%4];"
        : "=r"(r[0]), "=r"(r[1]), "=r"(r[2]), "=r"(r[3]) : "r"(addr));
}
__device__ __forceinline__ void mma_bf16(float* c, const uint32_t* a, uint32_t b0, uint32_t b1) {
    asm volatile(
        "mma.sync.aligned.m16n8k16.row.col.f32.bf16.bf16.f32 "
        "{%0,%1,%2,%3}, {%4,%5,%6,%7}, {%8,%9}, {%0,%1,%2,%3};"
        : "+f"(c[0]), "+f"(c[1]), "+f"(c[2]), "+f"(c[3])
        : "r"(a[0]), "r"(a[1]), "r"(a[2]), "r"(a[3]), "r"(b0), "r"(b1));
}

__device__ __forceinline__ uint32_t bf2u(__nv_bfloat162 v) {
    return *reinterpret_cast<uint32_t*>(&v);
}
// split float pair -> (hi bf16x2, lo bf16x2)
__device__ __forceinline__ void split2(float a, float b, uint32_t& hi, uint32_t& lo) {
    __nv_bfloat162 h = __floats2bfloat162_rn(a, b);
    float la = a - __low2float(h);
    float lb = b - __high2float(h);
    __nv_bfloat162 l = __floats2bfloat162_rn(la, lb);
    hi = bf2u(h); lo = bf2u(l);
}

__device__ __forceinline__ void grid_barrier() {
    __syncthreads();
    if (threadIdx.x == 0) {
        __threadfence();
        unsigned gen = *((volatile unsigned*)&g_bar_gen);
        int t = atomicAdd(&g_bar_count, 1);
        if (t == NBLK - 1) {
            g_bar_count = 0;
            __threadfence();
            atomicAdd(&g_bar_gen, 1u);
        } else {
            while (*((volatile unsigned*)&g_bar_gen) == gen) { }
        }
    }
    __syncthreads();
}

// Persistent MD-LSTM: one launch walks all 63 anti-diagonals.
// Block = 256 threads (8 warps). Tile: M=128 batches x N=64 gate rows
// (n = type*16 + jt; j = sb*16 + jt) x K=256, split-precision bf16 HMMA.
// WARP-INDEPENDENT rounds: each warp stages/consumes/writes ONLY its own
// 16 batch rows, so cells need no block-level sync — warps pipeline freely
// across the cells of a diagonal; only the per-diagonal grid barrier syncs.
__global__ __launch_bounds__(THREADS, 1)
void mdlstm_mma(const float* __restrict__ x,
                const float* __restrict__ w_ih,
                const float* __restrict__ w_hh,
                const float* __restrict__ bias,
                float*       __restrict__ out)
{
    extern __shared__ unsigned char smem[];
    const uint32_t smb  = smem_u32(smem);
    const int tid  = threadIdx.x;
    const int lane = tid & 31;
    const int wrp  = tid >> 5;            // 0..7
    const int sb    = blockIdx.x & 15;    // j-slice
    const int cslot = blockIdx.x >> 4;    // 0..8

    // ---- one-time: W slice (64 rows x 256 k) split into smem hi/lo ----
    {
        const int n    = tid >> 2;                 // 0..63
        const int kc   = (tid & 3) * 64;
        const int type = n >> 4, jt = n & 15;
        const int j    = sb * 16 + jt;
        const float* src = w_hh + ((size_t)(type * 256 + j) * 256 + kc);
        unsigned char* dhi = smem + SM_W_HI + n * PITCH + kc * 2;
        unsigned char* dlo = smem + SM_W_LO + n * PITCH + kc * 2;
        #pragma unroll 4
        for (int i = 0; i < 16; i++) {
            float4 v = *(const float4*)(src + i * 4);
            uint32_t h0, l0, h1, l1;
            split2(v.x, v.y, h0, l0);
            split2(v.z, v.w, h1, l1);
            *(uint2*)(dhi + i * 8) = make_uint2(h0, h1);
            *(uint2*)(dlo + i * 8) = make_uint2(l0, l1);
        }
    }
    if (tid < 64) {
        const int type = tid >> 4, jt = tid & 15;
        const int j = sb * 16 + jt;
        ((float*)(smem + SM_CONST))[tid]      = bias[type * 256 + j];
        ((float*)(smem + SM_CONST))[64 + tid] = w_ih[type * 256 + j];
    }
    __syncthreads();

    // per-lane ldmatrix address components
    const int m0 = wrp * 16;
    const uint32_t a_off = (uint32_t)(m0 + (lane & 15)) * PITCH + (lane >> 4) * 16;
    const uint32_t b_off = (uint32_t)(lane & 15) * PITCH + (lane >> 4) * 16;

    const int q  = lane & 3;
    const int g8 = lane >> 2;
    const float* sbias = (const float*)(smem + SM_CONST);
    const float* swih  = sbias + 64;

    for (int d = 0; d < 2 * HW - 1; d++) {
        const int n_d = (d < HW) ? (d + 1) : (2 * HW - 1 - d);
        const int r0  = (d > HW - 1) ? d - (HW - 1) : 0;

        for (int cell = cslot; cell < n_d; cell += CSLOTS) {
            const int r = r0 + cell, c = d - r;
            const int cell_id = r * HW + c;
            const bool has_up = (r > 0), has_left = (c > 0);

            float acc[8][4];
            #pragma unroll
            for (int f = 0; f < 8; f++)
                #pragma unroll
                for (int e = 0; e < 4; e++) acc[f][e] = 0.0f;

            if (has_up || has_left) {
                // ---- stage hsum for THIS WARP'S 16 rows, split -> smem ----
                {
                    const int row = m0 + (lane >> 1);    // warp-private rows
                    const int j0  = (lane & 1) * 128;
                    const float* pu = out + (size_t)row * (HW * HW * HID)
                                          + (size_t)(cell_id - HW) * HID + j0;
                    const float* pl = out + (size_t)row * (HW * HW * HID)
                                          + (size_t)(cell_id - 1) * HID + j0;
                    unsigned char* ahi = smem + SM_A_HI + row * PITCH + j0 * 2;
                    unsigned char* alo = smem + SM_A_LO + row * PITCH + j0 * 2;
                    #pragma unroll 8
                    for (int i = 0; i < 32; i++) {
                        float4 v = make_float4(0.f, 0.f, 0.f, 0.f);
                        if (has_up) {
                            float4 u = *(const float4*)(pu + i * 4);
                            v.x = u.x; v.y = u.y; v.z = u.z; v.w = u.w;
                        }
                        if (has_left) {
                            float4 l = *(const float4*)(pl + i * 4);
                            v.x += l.x; v.y += l.y; v.z += l.z; v.w += l.w;
                        }
                        uint32_t h0, l0, h1, l1;
                        split2(v.x, v.y, h0, l0);
                        split2(v.z, v.w, h1, l1);
                        *(uint2*)(ahi + i * 8) = make_uint2(h0, h1);
                        *(uint2*)(alo + i * 8) = make_uint2(l0, l1);
                    }
                }
                __syncwarp();                 // warp-local staging -> ldsm order
            }

            // ---- prefetch epilogue operands (s_up/s_left/x) before GEMM ----
            const size_t s_cur  = (size_t)cell_id * NB * HID;
            const size_t s_up   = (size_t)(cell_id - HW) * NB * HID;
            const size_t s_left = (size_t)(cell_id - 1) * NB * HID;

            float2 pss[2][2];          // [h][p] prefetched s_up+s_left partial sums
            float  pxp[2];             // [h] prefetched x
            #pragma unroll
            for (int h = 0; h < 2; h++) {
                const int b = m0 + g8 + h * 8;
                pxp[h] = x[b * (HW * HW) + cell_id];
                #pragma unroll
                for (int p = 0; p < 2; p++) {
                    const int j0e = sb * 16 + p * 8 + q * 2;
                    float2 ss = make_float2(0.f, 0.f);
                    if (has_up) {
                        float2 t = *(const float2*)&g_s[s_up + (size_t)b * HID + j0e];
                        ss.x += t.x; ss.y += t.y;
                    }
                    if (has_left) {
                        float2 t = *(const float2*)&g_s[s_left + (size_t)b * HID + j0e];
                        ss.x += t.x; ss.y += t.y;
                    }
                    pss[h][p] = ss;
                }
            }

            if (has_up || has_left) {
                // ---- GEMM: gates[b][n] = sum_k hsum[b][k] * W[n][k] ----
                #pragma unroll 2
                for (int kk = 0; kk < 16; kk++) {
                    const uint32_t ka = kk * 32;        // 16 bf16 = 32 B per k-step
                    uint32_t ah[4], al[4];
                    ldm_x4(ah, smb + SM_A_HI + a_off + ka);
                    ldm_x4(al, smb + SM_A_LO + a_off + ka);
                    #pragma unroll
                    for (int g = 0; g < 4; g++) {
                        uint32_t bh[4], bl[4];
                        ldm_x4(bh, smb + SM_W_HI + (uint32_t)g * 16 * PITCH + b_off + ka);
                        ldm_x4(bl, smb + SM_W_LO + (uint32_t)g * 16 * PITCH + b_off + ka);
                        mma_bf16(acc[g * 2],     ah, bh[0], bh[2]);
                        mma_bf16(acc[g * 2 + 1], ah, bh[1], bh[3]);
                        mma_bf16(acc[g * 2],     ah, bl[0], bl[2]);
                        mma_bf16(acc[g * 2 + 1], ah, bl[1], bl[3]);
                        mma_bf16(acc[g * 2],     al, bh[0], bh[2]);
                        mma_bf16(acc[g * 2 + 1], al, bh[1], bh[3]);
                    }
                }
            }

            // ---- epilogue: thread owns (2 b-rows) x (4 jt) x 4 gate types ----
            #pragma unroll
            for (int h = 0; h < 2; h++) {
                const int b = m0 + g8 + h * 8;
                const float xp = pxp[h];
                #pragma unroll
                for (int p = 0; p < 2; p++) {
                    const int jt0 = p * 8 + q * 2;
                    const int j0e = sb * 16 + jt0;
                    const float2 ssum = pss[h][p];

                    float sv[2], hv[2];
                    #pragma unroll
                    for (int cc = 0; cc < 2; cc++) {
                        const int jt = jt0 + cc;
                        const int e  = h * 2 + cc;
                        const float gi = acc[0 + p][e] + sbias[jt]      + xp * swih[jt];
                        const float gf = acc[2 + p][e] + sbias[16 + jt] + xp * swih[16 + jt];
                        const float gg = acc[4 + p][e] + sbias[32 + jt] + xp * swih[32 + jt];
                        const float go = acc[6 + p][e] + sbias[48 + jt] + xp * swih[48 + jt];

                        const float iv = fsigmoid(gi);
                        const float fv = fsigmoid(gf);
                        const float gv = ftanh(gg);
                        const float ov = fsigmoid(go);

                        const float ss = (cc == 0) ? ssum.x : ssum.y;
                        sv[cc] = fv * ss + iv * gv;
                        hv[cc] = ov * ftanh(sv[cc]);
                    }
                    *(float2*)&g_s[s_cur + (size_t)b * HID + j0e] = make_float2(sv[0], sv[1]);
                    *(float2*)&out[(size_t)b * (HW * HW * HID)
                                   + (size_t)cell_id * HID + j0e]  = make_float2(hv[0], hv[1]);
                }
            }
            // no block sync: each warp touches only its own A rows / batches
        }
        grid_barrier();
    }
}

extern "C" void kernel_launch(void* const* d_in, const int* in_sizes, int n_in,
                              void* d_out, int out_size) {
    const float* x    = (const float*)d_in[0];
    const float* w_ih = (const float*)d_in[1];
    const float* w_hh = (const float*)d_in[2];
    const float* bias = (const float*)d_in[3];
    float* out = (float*)d_out;

    cudaFuncSetAttribute(mdlstm_mma,
                         cudaFuncAttributeMaxDynamicSharedMemorySize, SMEM_TOTAL);
    mdlstm_mma<<<NBLK, THREADS, SMEM_TOTAL>>>(x, w_ih, w_hh, bias, out);
}